// round 2
// baseline (speedup 1.0000x reference)
#include <cuda_runtime.h>
#include <math.h>

// Problem constants
#define L_ 6
#define B_ 16
#define T_ 2048
#define D_ 768
#define V_ 50280
#define LB_ 96                 // L_*B_
#define WPB_ 1572              // ceil(V_/32)
#define NCHUNK_ 9
#define NEG_INF __int_as_float(0xff800000)

// Scratch (static device globals — no allocation)
__device__ unsigned g_present[B_ * WPB_];
__device__ int      g_list[B_ * T_];
__device__ int      g_cnt[B_];
__device__ float    g_h[LB_ * D_];
__device__ float    g_pm[LB_ * NCHUNK_];
__device__ float    g_ps[LB_ * NCHUNK_];
__device__ int      g_pa[LB_ * NCHUNK_];
__device__ float    g_lt[LB_];

// ---------------------------------------------------------------------------
// 1) zero present bitmask
__global__ void zero_present_k() {
    int i = blockIdx.x * blockDim.x + threadIdx.x;
    if (i < B_ * WPB_) g_present[i] = 0u;
}

// 2) scatter input_ids into bitmask
__global__ void scatter_k(const int* __restrict__ ids) {
    int i = blockIdx.x * blockDim.x + threadIdx.x;
    if (i < B_ * T_) {
        int b = i >> 11;               // T_=2048
        int id = ids[i];
        atomicOr(&g_present[b * WPB_ + (id >> 5)], 1u << (id & 31));
    }
}

// 3) deterministic compaction: per-b list of present ids in ascending order
//    1 CTA, 512 threads = 16 warps, warp w handles batch b=w
__global__ void compact_k() {
    int tid = threadIdx.x;
    int b = tid >> 5;
    int lane = tid & 31;
    const int CW = (WPB_ + 31) / 32;   // 50 words per lane
    int w0 = lane * CW;
    int w1 = min(WPB_, w0 + CW);
    int c = 0;
    for (int wi = w0; wi < w1; wi++) c += __popc(g_present[b * WPB_ + wi]);
    int inc = c;
    #pragma unroll
    for (int off = 1; off < 32; off <<= 1) {
        int n = __shfl_up_sync(0xffffffffu, inc, off);
        if (lane >= off) inc += n;
    }
    int base = inc - c;
    int total = __shfl_sync(0xffffffffu, inc, 31);
    if (lane == 0) g_cnt[b] = total;
    int pos = base;
    for (int wi = w0; wi < w1; wi++) {
        unsigned bits = g_present[b * WPB_ + wi];
        while (bits) {
            int bit = __ffs(bits) - 1;
            g_list[b * T_ + pos++] = wi * 32 + bit;
            bits &= bits - 1;
        }
    }
}

// 4) gather h rows: h[l*B+b][:] = x[l, b, ans_starts[b]-1, :]
__global__ void gather_h_k(const float* __restrict__ x, const int* __restrict__ as) {
    int r = blockIdx.x;                // 0..95
    int l = r / B_, b = r % B_;
    int t = as[b] - 1;
    t = max(0, min(t, T_ - 1));
    const float4* src = reinterpret_cast<const float4*>(x) +
                        (((size_t)l * B_ + b) * T_ + t) * (D_ / 4);
    float4* dst = reinterpret_cast<float4*>(g_h) + (size_t)r * (D_ / 4);
    dst[threadIdx.x] = src[threadIdx.x];   // 192 threads, 192 float4 per row
}

// 5) main: per (b, chunk) CTA. Each thread owns one present token v,
//    computes 6 logits (dot with h rows in smem), captures logit@target,
//    then block reduces (max, argmax-lowest-idx, sum-exp) per l.
__global__ __launch_bounds__(256) void main_k(const float* __restrict__ w,
                                              const int* __restrict__ ct) {
    __shared__ float sH[L_ * D_];      // 18 KB
    __shared__ float s_m[8];
    __shared__ int   s_a[8];
    __shared__ float s_s[8];

    int b = blockIdx.y, c = blockIdx.x;
    int tid = threadIdx.x, lane = tid & 31, wrp = tid >> 5;

    // stage h rows for this b (broadcast-read later)
    {
        const float4* hg = reinterpret_cast<const float4*>(g_h);
        float4* sH4 = reinterpret_cast<float4*>(sH);
        for (int i = tid; i < L_ * (D_ / 4); i += 256) {
            int l = i / (D_ / 4), j = i % (D_ / 4);
            sH4[i] = hg[((size_t)l * B_ + b) * (D_ / 4) + j];
        }
    }
    __syncthreads();

    int cnt = g_cnt[b];
    int sz = (cnt + NCHUNK_ - 1) / NCHUNK_;   // <= 228 <= 256 since cnt <= 2048
    int start = c * sz;
    int end = min(cnt, start + sz);
    int e = start + tid;

    float acc[L_];
    #pragma unroll
    for (int l = 0; l < L_; l++) acc[l] = 0.f;
    int v = -1;

    if (e < end) {
        v = g_list[b * T_ + e];
        const float4* wr = reinterpret_cast<const float4*>(w) + (size_t)v * (D_ / 4);
        const float4* hr = reinterpret_cast<const float4*>(sH);
        for (int j = 0; j < D_ / 4; j += 8) {
            float4 wv[8];
            #pragma unroll
            for (int u = 0; u < 8; u++) wv[u] = wr[j + u];   // MLP=8
            #pragma unroll
            for (int u = 0; u < 8; u++) {
                #pragma unroll
                for (int l = 0; l < L_; l++) {
                    float4 hv = hr[l * (D_ / 4) + j + u];    // smem broadcast
                    acc[l] = fmaf(wv[u].x, hv.x, acc[l]);
                    acc[l] = fmaf(wv[u].y, hv.y, acc[l]);
                    acc[l] = fmaf(wv[u].z, hv.z, acc[l]);
                    acc[l] = fmaf(wv[u].w, hv.w, acc[l]);
                }
            }
        }
        // capture logit at target (tgt is always in the present list of its b)
        #pragma unroll
        for (int l = 0; l < L_; l++)
            if (v == ct[b * L_ + l]) g_lt[l * B_ + b] = acc[l];
    }

    bool has = (v >= 0);
    for (int l = 0; l < L_; l++) {
        // --- block max + lowest-index argmax ---
        float m = has ? acc[l] : NEG_INF;
        int am = has ? v : 0x7fffffff;
        #pragma unroll
        for (int off = 16; off; off >>= 1) {
            float om = __shfl_xor_sync(0xffffffffu, m, off);
            int   oa = __shfl_xor_sync(0xffffffffu, am, off);
            if (om > m || (om == m && oa < am)) { m = om; am = oa; }
        }
        if (lane == 0) { s_m[wrp] = m; s_a[wrp] = am; }
        __syncthreads();
        if (wrp == 0) {
            float m2 = (lane < 8) ? s_m[lane] : NEG_INF;
            int   a2 = (lane < 8) ? s_a[lane] : 0x7fffffff;
            #pragma unroll
            for (int off = 16; off; off >>= 1) {
                float om = __shfl_xor_sync(0xffffffffu, m2, off);
                int   oa = __shfl_xor_sync(0xffffffffu, a2, off);
                if (om > m2 || (om == m2 && oa < a2)) { m2 = om; a2 = oa; }
            }
            if (lane == 0) { s_m[0] = m2; s_a[0] = a2; }
        }
        __syncthreads();
        float M = s_m[0];
        int AM = s_a[0];

        // --- block sum of exp(logit - M) ---
        float sv = has ? expf(acc[l] - M) : 0.f;
        #pragma unroll
        for (int off = 16; off; off >>= 1)
            sv += __shfl_xor_sync(0xffffffffu, sv, off);
        if (lane == 0) s_s[wrp] = sv;
        __syncthreads();
        if (tid == 0) {
            float S = 0.f;
            #pragma unroll
            for (int i = 0; i < 8; i++) S += s_s[i];
            int p = (l * B_ + b) * NCHUNK_ + c;
            g_pm[p] = M; g_ps[p] = S; g_pa[p] = AM;
        }
        __syncthreads();   // protect smem reuse for next l
    }
}

// 6) final: merge chunk partials, compute nll/valid/acc and the 3 outputs
__global__ void final_k(const int* __restrict__ ct, const int* __restrict__ as,
                        float* __restrict__ out) {
    __shared__ float s_nll[LB_], s_acc[LB_], s_val[LB_];
    int tid = threadIdx.x;
    if (tid < LB_) {
        int l = tid / B_, b = tid % B_;
        float M = NEG_INF, S = 0.f;
        int A = 0x7fffffff;
        for (int c = 0; c < NCHUNK_; c++) {
            int p = tid * NCHUNK_ + c;
            float pm = g_pm[p], ps = g_ps[p];
            int pa = g_pa[p];
            if (pm > M) {
                S = S * expf(M - pm) + ps;   // expf(-inf)=0 handles first merge
                M = pm; A = pa;
            } else {
                if (ps > 0.f) S += ps * expf(pm - M);
                if (pm == M && pa < A) A = pa;
            }
        }
        int tgt = ct[b * L_ + l];
        float lse = M + logf(S);
        float nll = lse - g_lt[tid];
        bool present = (g_present[b * WPB_ + (tgt >> 5)] >> (tgt & 31)) & 1u;
        int a0 = as[b];
        bool valid = present && (a0 >= 1) && (a0 < T_);
        s_nll[tid] = valid ? nll : 0.f;
        s_acc[tid] = (valid && (A == tgt)) ? 1.f : 0.f;
        s_val[tid] = valid ? 1.f : 0.f;
    }
    __syncthreads();
    if (tid == 0) {
        float sum_loss = 0.f, sum_acc = 0.f, nvl = 0.f, fin = 0.f;
        for (int l = 0; l < L_; l++) {
            float cnt = 0.f, ls = 0.f, ac = 0.f;
            for (int b = 0; b < B_; b++) {
                cnt += s_val[l * B_ + b];
                ls  += s_nll[l * B_ + b];
                ac  += s_acc[l * B_ + b];
            }
            float den = fmaxf(cnt, 1.f);
            float ll = ls / den, la = ac / den;
            if (cnt > 0.f) { sum_loss += ll; sum_acc += la; nvl += 1.f; }
            if (l == L_ - 1) fin = la;
        }
        float nv = fmaxf(nvl, 1.f);
        out[0] = sum_loss / nv;
        out[1] = sum_acc / nv;
        out[2] = fin;
    }
}

// ---------------------------------------------------------------------------
extern "C" void kernel_launch(void* const* d_in, const int* in_sizes, int n_in,
                              void* d_out, int out_size) {
    const float* x   = (const float*)d_in[0];   // x_normed (L,B,T,D) f32
    const float* w   = (const float*)d_in[1];   // lm_head_w (V,D) f32
    const int*   ids = (const int*)d_in[2];     // input_ids (B,T) i32
    const int*   ct  = (const int*)d_in[3];     // chain_targets (B,L) i32
    const int*   as  = (const int*)d_in[4];     // ans_starts (B,) i32
    float* out = (float*)d_out;

    zero_present_k<<<(B_ * WPB_ + 255) / 256, 256>>>();
    scatter_k<<<(B_ * T_ + 255) / 256, 256>>>(ids);
    gather_h_k<<<LB_, D_ / 4>>>(x, as);
    compact_k<<<1, 512>>>();
    main_k<<<dim3(NCHUNK_, B_), 256>>>(w, ct);
    final_k<<<1, 128>>>(ct, as, out);
}

// round 4
// speedup vs baseline: 1.6428x; 1.6428x over previous
#include <cuda_runtime.h>
#include <math.h>

// Problem constants
#define L_ 6
#define B_ 16
#define T_ 2048
#define D_ 768
#define V_ 50280
#define LB_ 96                 // L_*B_
#define WPB_ 1572              // ceil(V_/32)
#define NCHUNK_ 9
#define NEG_INF __int_as_float(0xff800000)

// Scratch (static device globals — no allocation)
__device__ unsigned g_present[B_ * WPB_];
__device__ int      g_list[B_ * T_];
__device__ int      g_cnt[B_];
__device__ float    g_pm[LB_ * NCHUNK_];
__device__ float    g_ps[LB_ * NCHUNK_];
__device__ int      g_pa[LB_ * NCHUNK_];
__device__ float    g_lt[LB_];

// ---------------------------------------------------------------------------
// 1) zero present bitmask
__global__ void zero_present_k() {
    int i = blockIdx.x * blockDim.x + threadIdx.x;
    if (i < B_ * WPB_) g_present[i] = 0u;
}

// 2) scatter input_ids into bitmask
__global__ void scatter_k(const int* __restrict__ ids) {
    int i = blockIdx.x * blockDim.x + threadIdx.x;
    if (i < B_ * T_) {
        int b = i >> 11;               // T_=2048
        int id = ids[i];
        atomicOr(&g_present[b * WPB_ + (id >> 5)], 1u << (id & 31));
    }
}

// 3) parallel deterministic compaction: CTA per batch, 256 threads, block scan.
//    Produces ascending token list per b + count.
__global__ __launch_bounds__(256) void compact_k() {
    __shared__ int wsum[8];
    int b = blockIdx.x;
    int tid = threadIdx.x, lane = tid & 31, wrp = tid >> 5;
    const int CW = 7;                  // 256*7 = 1792 >= 1572
    int w0 = tid * CW;
    int w1 = min(WPB_, w0 + CW);
    int c = 0;
    for (int wi = w0; wi < w1; wi++) c += __popc(g_present[b * WPB_ + wi]);
    // warp inclusive scan
    int inc = c;
    #pragma unroll
    for (int off = 1; off < 32; off <<= 1) {
        int n = __shfl_up_sync(0xffffffffu, inc, off);
        if (lane >= off) inc += n;
    }
    if (lane == 31) wsum[wrp] = inc;
    __syncthreads();
    // scan the 8 warp totals (warp 0)
    if (wrp == 0) {
        int v = (lane < 8) ? wsum[lane] : 0;
        int iv = v;
        #pragma unroll
        for (int off = 1; off < 8; off <<= 1) {
            int n = __shfl_up_sync(0xffffffffu, iv, off);
            if (lane >= off) iv += n;
        }
        if (lane < 8) wsum[lane] = iv - v;    // exclusive warp base
        if (lane == 7 && b >= 0) g_cnt[b] = iv;
    }
    __syncthreads();
    int pos = wsum[wrp] + inc - c;            // global exclusive base for this thread
    for (int wi = w0; wi < w1; wi++) {
        unsigned bits = g_present[b * WPB_ + wi];
        while (bits) {
            int bit = __ffs(bits) - 1;
            g_list[b * T_ + pos++] = wi * 32 + bit;
            bits &= bits - 1;
        }
    }
}

// 4) main: CTA = (chunk c, batch b). Warp-per-token, coalesced W reads,
//    h rows held in per-lane registers (each lane owns a 24-elem slice of
//    all 6 h rows). Butterfly-reduce logit, online softmax per l in regs,
//    cross-warp merge in smem -> per-chunk partials.
__global__ __launch_bounds__(256, 1) void main_k(const float* __restrict__ x,
                                                 const float* __restrict__ w,
                                                 const int* __restrict__ ct,
                                                 const int* __restrict__ as) {
    __shared__ float sm[L_ * 8];
    __shared__ float ss[L_ * 8];
    __shared__ int   sa[L_ * 8];

    int b = blockIdx.y, c = blockIdx.x;
    int tid = threadIdx.x, lane = tid & 31, wrp = tid >> 5;

    // per-lane register-resident h slices: hreg[l][u] = x4[l,b,t, u*32+lane]
    int t = as[b] - 1;
    t = max(0, min(t, T_ - 1));
    const float4* x4 = reinterpret_cast<const float4*>(x);
    float4 hreg[L_][6];
    #pragma unroll
    for (int l = 0; l < L_; l++) {
        size_t base = (((size_t)l * B_ + b) * T_ + t) * (D_ / 4);
        #pragma unroll
        for (int u = 0; u < 6; u++)
            hreg[l][u] = x4[base + u * 32 + lane];
    }
    int ctv[L_];
    #pragma unroll
    for (int l = 0; l < L_; l++) ctv[l] = ct[b * L_ + l];

    int cnt = g_cnt[b];
    int sz = (cnt + NCHUNK_ - 1) / NCHUNK_;
    int start = c * sz;
    int end = min(cnt, start + sz);

    float m[L_], s[L_];
    int am[L_];
    #pragma unroll
    for (int l = 0; l < L_; l++) { m[l] = NEG_INF; s[l] = 0.f; am[l] = 0x7fffffff; }

    const float4* w4 = reinterpret_cast<const float4*>(w);
    for (int e = start + wrp; e < end; e += 8) {
        int v = g_list[b * T_ + e];
        const float4* wr = w4 + (size_t)v * (D_ / 4);
        float4 wv[6];
        #pragma unroll
        for (int u = 0; u < 6; u++) wv[u] = wr[u * 32 + lane];   // MLP=6, coalesced

        float acc[L_];
        #pragma unroll
        for (int l = 0; l < L_; l++) acc[l] = 0.f;
        #pragma unroll
        for (int u = 0; u < 6; u++) {
            #pragma unroll
            for (int l = 0; l < L_; l++) {
                acc[l] = fmaf(wv[u].x, hreg[l][u].x, acc[l]);
                acc[l] = fmaf(wv[u].y, hreg[l][u].y, acc[l]);
                acc[l] = fmaf(wv[u].z, hreg[l][u].z, acc[l]);
                acc[l] = fmaf(wv[u].w, hreg[l][u].w, acc[l]);
            }
        }
        // butterfly: all lanes end with the full dot
        #pragma unroll
        for (int l = 0; l < L_; l++) {
            #pragma unroll
            for (int off = 16; off; off >>= 1)
                acc[l] += __shfl_xor_sync(0xffffffffu, acc[l], off);
        }
        // capture logit at target
        #pragma unroll
        for (int l = 0; l < L_; l++)
            if (v == ctv[l] && lane == 0) g_lt[l * B_ + b] = acc[l];
        // online softmax stats (identical on all lanes; v ascending per warp)
        #pragma unroll
        for (int l = 0; l < L_; l++) {
            float lg = acc[l];
            if (lg > m[l]) {
                s[l] = s[l] * __expf(m[l] - lg) + 1.f;   // expf(-inf)=0 on first
                m[l] = lg;
                am[l] = v;
            } else {
                s[l] += __expf(lg - m[l]);
            }
        }
    }

    if (lane == 0) {
        #pragma unroll
        for (int l = 0; l < L_; l++) {
            sm[l * 8 + wrp] = m[l];
            ss[l * 8 + wrp] = s[l];
            sa[l * 8 + wrp] = am[l];
        }
    }
    __syncthreads();
    if (tid < L_) {
        int l = tid;
        float M = NEG_INF, S = 0.f;
        int A = 0x7fffffff;
        #pragma unroll
        for (int wi = 0; wi < 8; wi++) {
            float pm = sm[l * 8 + wi], ps = ss[l * 8 + wi];
            int pa = sa[l * 8 + wi];
            if (pm > M) {
                S = S * __expf(M - pm) + ps;
                M = pm; A = pa;
            } else if (ps > 0.f) {
                S += ps * __expf(pm - M);
                if (pm == M && pa < A) A = pa;
            }
        }
        int p = (l * B_ + b) * NCHUNK_ + c;
        g_pm[p] = M; g_ps[p] = S; g_pa[p] = A;
    }
}

// 5) final: merge chunk partials, compute nll/valid/acc and the 3 outputs
__global__ void final_k(const int* __restrict__ ct, const int* __restrict__ as,
                        float* __restrict__ out) {
    __shared__ float s_nll[LB_], s_acc[LB_], s_val[LB_];
    int tid = threadIdx.x;
    if (tid < LB_) {
        int l = tid / B_, b = tid % B_;
        float M = NEG_INF, S = 0.f;
        int A = 0x7fffffff;
        for (int c = 0; c < NCHUNK_; c++) {
            int p = tid * NCHUNK_ + c;
            float pm = g_pm[p], ps = g_ps[p];
            int pa = g_pa[p];
            if (pm > M) {
                S = S * expf(M - pm) + ps;
                M = pm; A = pa;
            } else {
                if (ps > 0.f) S += ps * expf(pm - M);
                if (pm == M && pa < A) A = pa;
            }
        }
        int tgt = ct[b * L_ + l];
        float lse = M + logf(S);
        float nll = lse - g_lt[tid];
        bool present = (g_present[b * WPB_ + (tgt >> 5)] >> (tgt & 31)) & 1u;
        int a0 = as[b];
        bool valid = present && (a0 >= 1) && (a0 < T_);
        s_nll[tid] = valid ? nll : 0.f;
        s_acc[tid] = (valid && (A == tgt)) ? 1.f : 0.f;
        s_val[tid] = valid ? 1.f : 0.f;
    }
    __syncthreads();
    if (tid == 0) {
        float sum_loss = 0.f, sum_acc = 0.f, nvl = 0.f, fin = 0.f;
        for (int l = 0; l < L_; l++) {
            float cnt = 0.f, ls = 0.f, ac = 0.f;
            for (int b = 0; b < B_; b++) {
                cnt += s_val[l * B_ + b];
                ls  += s_nll[l * B_ + b];
                ac  += s_acc[l * B_ + b];
            }
            float den = fmaxf(cnt, 1.f);
            float ll = ls / den, la = ac / den;
            if (cnt > 0.f) { sum_loss += ll; sum_acc += la; nvl += 1.f; }
            if (l == L_ - 1) fin = la;
        }
        float nv = fmaxf(nvl, 1.f);
        out[0] = sum_loss / nv;
        out[1] = sum_acc / nv;
        out[2] = fin;
    }
}

// ---------------------------------------------------------------------------
extern "C" void kernel_launch(void* const* d_in, const int* in_sizes, int n_in,
                              void* d_out, int out_size) {
    const float* x   = (const float*)d_in[0];   // x_normed (L,B,T,D) f32
    const float* w   = (const float*)d_in[1];   // lm_head_w (V,D) f32
    const int*   ids = (const int*)d_in[2];     // input_ids (B,T) i32
    const int*   ct  = (const int*)d_in[3];     // chain_targets (B,L) i32
    const int*   as  = (const int*)d_in[4];     // ans_starts (B,) i32
    float* out = (float*)d_out;

    zero_present_k<<<(B_ * WPB_ + 255) / 256, 256>>>();
    scatter_k<<<(B_ * T_ + 255) / 256, 256>>>(ids);
    compact_k<<<B_, 256>>>();
    main_k<<<dim3(NCHUNK_, B_), 256>>>(x, w, ct, as);
    final_k<<<1, 128>>>(ct, as, out);
}

// round 5
// speedup vs baseline: 2.2226x; 1.3529x over previous
#include <cuda_runtime.h>
#include <math.h>

// Problem constants
#define L_ 6
#define B_ 16
#define T_ 2048
#define D_ 768
#define V_ 50280
#define LB_ 96                 // L_*B_
#define WPB_ 1572              // ceil(V_/32)
#define NCHUNK_ 9
#define LSPLIT_ 2
#define LPER_ 3                // L_ / LSPLIT_
#define NEG_INF __int_as_float(0xff800000)

// Scratch (static device globals — no allocation)
__device__ unsigned g_present[B_ * WPB_];
__device__ int      g_list[B_ * T_];
__device__ int      g_cnt[B_];
__device__ float    g_pm[LB_ * NCHUNK_];
__device__ float    g_ps[LB_ * NCHUNK_];
__device__ int      g_pa[LB_ * NCHUNK_];
__device__ float    g_lt[LB_];

// ---------------------------------------------------------------------------
// 1) zero present bitmask
__global__ void zero_present_k() {
    int i = blockIdx.x * blockDim.x + threadIdx.x;
    if (i < B_ * WPB_) g_present[i] = 0u;
}

// 2) scatter input_ids into bitmask
__global__ void scatter_k(const int* __restrict__ ids) {
    int i = blockIdx.x * blockDim.x + threadIdx.x;
    if (i < B_ * T_) {
        int b = i >> 11;               // T_=2048
        int id = ids[i];
        atomicOr(&g_present[b * WPB_ + (id >> 5)], 1u << (id & 31));
    }
}

// 3) parallel deterministic compaction: CTA per batch, 256 threads, block scan.
__global__ __launch_bounds__(256) void compact_k() {
    __shared__ int wsum[8];
    int b = blockIdx.x;
    int tid = threadIdx.x, lane = tid & 31, wrp = tid >> 5;
    const int CW = 7;                  // 256*7 = 1792 >= 1572
    int w0 = tid * CW;
    int w1 = min(WPB_, w0 + CW);
    int c = 0;
    for (int wi = w0; wi < w1; wi++) c += __popc(g_present[b * WPB_ + wi]);
    int inc = c;
    #pragma unroll
    for (int off = 1; off < 32; off <<= 1) {
        int n = __shfl_up_sync(0xffffffffu, inc, off);
        if (lane >= off) inc += n;
    }
    if (lane == 31) wsum[wrp] = inc;
    __syncthreads();
    if (wrp == 0) {
        int v = (lane < 8) ? wsum[lane] : 0;
        int iv = v;
        #pragma unroll
        for (int off = 1; off < 8; off <<= 1) {
            int n = __shfl_up_sync(0xffffffffu, iv, off);
            if (lane >= off) iv += n;
        }
        if (lane < 8) wsum[lane] = iv - v;
        if (lane == 7) g_cnt[b] = iv;
    }
    __syncthreads();
    int pos = wsum[wrp] + inc - c;
    for (int wi = w0; wi < w1; wi++) {
        unsigned bits = g_present[b * WPB_ + wi];
        while (bits) {
            int bit = __ffs(bits) - 1;
            g_list[b * T_ + pos++] = wi * 32 + bit;
            bits &= bits - 1;
        }
    }
}

// 4) main: CTA = (chunk c, batch b, l-half lh). Warp-per-token, coalesced W
//    reads, 3 h rows per lane in registers (72 regs). 2 CTAs/SM, 16 warps/SM.
//    Sibling CTA (other lh) reads the same W rows concurrently -> L2 hit.
__global__ __launch_bounds__(256, 2) void main_k(const float* __restrict__ x,
                                                 const float* __restrict__ w,
                                                 const int* __restrict__ ct,
                                                 const int* __restrict__ as) {
    __shared__ float sm[LPER_ * 8];
    __shared__ float ss[LPER_ * 8];
    __shared__ int   sa[LPER_ * 8];

    int b = blockIdx.y, c = blockIdx.x, lh = blockIdx.z;
    int l0 = lh * LPER_;
    int tid = threadIdx.x, lane = tid & 31, wrp = tid >> 5;

    // per-lane register h slices for our 3 loops
    int t = as[b] - 1;
    t = max(0, min(t, T_ - 1));
    const float4* x4 = reinterpret_cast<const float4*>(x);
    float4 hreg[LPER_][6];
    #pragma unroll
    for (int j = 0; j < LPER_; j++) {
        size_t base = (((size_t)(l0 + j) * B_ + b) * T_ + t) * (D_ / 4);
        #pragma unroll
        for (int u = 0; u < 6; u++)
            hreg[j][u] = x4[base + u * 32 + lane];
    }
    int ctv[LPER_];
    #pragma unroll
    for (int j = 0; j < LPER_; j++) ctv[j] = ct[b * L_ + l0 + j];

    int cnt = g_cnt[b];
    int sz = (cnt + NCHUNK_ - 1) / NCHUNK_;
    int start = c * sz;
    int end = min(cnt, start + sz);

    float m[LPER_], s[LPER_];
    int am[LPER_];
    #pragma unroll
    for (int j = 0; j < LPER_; j++) { m[j] = NEG_INF; s[j] = 0.f; am[j] = 0x7fffffff; }

    const float4* w4 = reinterpret_cast<const float4*>(w);
    const int* lst = g_list + b * T_;

    // deferred-update software pipeline: while this token's W row streams in,
    // fold the PREVIOUS token's logits into the online-softmax state.
    float accp[LPER_];
    int vp = -1;
    int v = (start + wrp < end) ? lst[start + wrp] : -1;

    for (int e = start + wrp; e < end; e += 8) {
        const float4* wr = w4 + (size_t)v * (D_ / 4);
        float4 wv[6];
        #pragma unroll
        for (int u = 0; u < 6; u++) wv[u] = wr[u * 32 + lane];   // MLP=6

        int vn = (e + 8 < end) ? lst[e + 8] : -1;

        // overlap: previous token's softmax update (expf/compare) under load latency
        if (vp >= 0) {
            #pragma unroll
            for (int j = 0; j < LPER_; j++) {
                float lg = accp[j];
                if (lg > m[j]) {
                    s[j] = s[j] * __expf(m[j] - lg) + 1.f;
                    m[j] = lg;
                    am[j] = vp;
                } else {
                    s[j] += __expf(lg - m[j]);
                }
            }
        }

        float acc[LPER_];
        #pragma unroll
        for (int j = 0; j < LPER_; j++) acc[j] = 0.f;
        #pragma unroll
        for (int u = 0; u < 6; u++) {
            #pragma unroll
            for (int j = 0; j < LPER_; j++) {
                acc[j] = fmaf(wv[u].x, hreg[j][u].x, acc[j]);
                acc[j] = fmaf(wv[u].y, hreg[j][u].y, acc[j]);
                acc[j] = fmaf(wv[u].z, hreg[j][u].z, acc[j]);
                acc[j] = fmaf(wv[u].w, hreg[j][u].w, acc[j]);
            }
        }
        #pragma unroll
        for (int j = 0; j < LPER_; j++) {
            #pragma unroll
            for (int off = 16; off; off >>= 1)
                acc[j] += __shfl_xor_sync(0xffffffffu, acc[j], off);
        }
        #pragma unroll
        for (int j = 0; j < LPER_; j++)
            if (v == ctv[j] && lane == 0) g_lt[(l0 + j) * B_ + b] = acc[j];

        #pragma unroll
        for (int j = 0; j < LPER_; j++) accp[j] = acc[j];
        vp = v;
        v = vn;
    }
    // drain last token
    if (vp >= 0) {
        #pragma unroll
        for (int j = 0; j < LPER_; j++) {
            float lg = accp[j];
            if (lg > m[j]) {
                s[j] = s[j] * __expf(m[j] - lg) + 1.f;
                m[j] = lg;
                am[j] = vp;
            } else {
                s[j] += __expf(lg - m[j]);
            }
        }
    }

    if (lane == 0) {
        #pragma unroll
        for (int j = 0; j < LPER_; j++) {
            sm[j * 8 + wrp] = m[j];
            ss[j * 8 + wrp] = s[j];
            sa[j * 8 + wrp] = am[j];
        }
    }
    __syncthreads();
    if (tid < LPER_) {
        int j = tid;
        float M = NEG_INF, S = 0.f;
        int A = 0x7fffffff;
        #pragma unroll
        for (int wi = 0; wi < 8; wi++) {
            float pm = sm[j * 8 + wi], ps = ss[j * 8 + wi];
            int pa = sa[j * 8 + wi];
            if (pm > M) {
                S = S * __expf(M - pm) + ps;
                M = pm; A = pa;
            } else if (ps > 0.f) {
                S += ps * __expf(pm - M);
                if (pm == M && pa < A) A = pa;
            }
        }
        int p = ((l0 + j) * B_ + b) * NCHUNK_ + c;
        g_pm[p] = M; g_ps[p] = S; g_pa[p] = A;
    }
}

// 5) final: merge chunk partials, compute nll/valid/acc and the 3 outputs
__global__ void final_k(const int* __restrict__ ct, const int* __restrict__ as,
                        float* __restrict__ out) {
    __shared__ float s_nll[LB_], s_acc[LB_], s_val[LB_];
    int tid = threadIdx.x;
    if (tid < LB_) {
        int l = tid / B_, b = tid % B_;
        float M = NEG_INF, S = 0.f;
        int A = 0x7fffffff;
        for (int c = 0; c < NCHUNK_; c++) {
            int p = tid * NCHUNK_ + c;
            float pm = g_pm[p], ps = g_ps[p];
            int pa = g_pa[p];
            if (pm > M) {
                S = S * expf(M - pm) + ps;
                M = pm; A = pa;
            } else {
                if (ps > 0.f) S += ps * expf(pm - M);
                if (pm == M && pa < A) A = pa;
            }
        }
        int tgt = ct[b * L_ + l];
        float lse = M + logf(S);
        float nll = lse - g_lt[tid];
        bool present = (g_present[b * WPB_ + (tgt >> 5)] >> (tgt & 31)) & 1u;
        int a0 = as[b];
        bool valid = present && (a0 >= 1) && (a0 < T_);
        s_nll[tid] = valid ? nll : 0.f;
        s_acc[tid] = (valid && (A == tgt)) ? 1.f : 0.f;
        s_val[tid] = valid ? 1.f : 0.f;
    }
    __syncthreads();
    if (tid == 0) {
        float sum_loss = 0.f, sum_acc = 0.f, nvl = 0.f, fin = 0.f;
        for (int l = 0; l < L_; l++) {
            float cnt = 0.f, ls = 0.f, ac = 0.f;
            for (int b = 0; b < B_; b++) {
                cnt += s_val[l * B_ + b];
                ls  += s_nll[l * B_ + b];
                ac  += s_acc[l * B_ + b];
            }
            float den = fmaxf(cnt, 1.f);
            float ll = ls / den, la = ac / den;
            if (cnt > 0.f) { sum_loss += ll; sum_acc += la; nvl += 1.f; }
            if (l == L_ - 1) fin = la;
        }
        float nv = fmaxf(nvl, 1.f);
        out[0] = sum_loss / nv;
        out[1] = sum_acc / nv;
        out[2] = fin;
    }
}

// ---------------------------------------------------------------------------
extern "C" void kernel_launch(void* const* d_in, const int* in_sizes, int n_in,
                              void* d_out, int out_size) {
    const float* x   = (const float*)d_in[0];   // x_normed (L,B,T,D) f32
    const float* w   = (const float*)d_in[1];   // lm_head_w (V,D) f32
    const int*   ids = (const int*)d_in[2];     // input_ids (B,T) i32
    const int*   ct  = (const int*)d_in[3];     // chain_targets (B,L) i32
    const int*   as  = (const int*)d_in[4];     // ans_starts (B,) i32
    float* out = (float*)d_out;

    zero_present_k<<<(B_ * WPB_ + 255) / 256, 256>>>();
    scatter_k<<<(B_ * T_ + 255) / 256, 256>>>(ids);
    compact_k<<<B_, 256>>>();
    main_k<<<dim3(NCHUNK_, B_, LSPLIT_), 256>>>(x, w, ct, as);
    final_k<<<1, 128>>>(ct, as, out);
}